// round 10
// baseline (speedup 1.0000x reference)
#include <cuda_runtime.h>
#include <cuda_bf16.h>
#include <cuda_fp16.h>
#include <cstdint>

#define N_NODES 8192
#define FIN     512
#define FOUT    256
#define BKC     64                   // K-chunk (j per mainloop iter)
#define NCHUNK  (N_NODES / BKC)      // 128
#define NWORDS  (N_NODES / 32)       // 256 mask words per row

// ---------------------------------------------------------------------------
// Device scratch
// ---------------------------------------------------------------------------
__device__ float g_h[(size_t)N_NODES * FOUT];          // 8 MB   h = x@W
__device__ float g_s[2 * N_NODES];                     // s_src | s_dst
__device__ float g_smax;                               // max_j s_dst
__device__ __half g_hT[(size_t)FOUT * N_NODES];        // 4 MB   h^T fp16
__device__ uint32_t g_maskR[(size_t)N_NODES * NWORDS]; // 8 MB   mask[i][jw]
__device__ __half g_w[(size_t)N_NODES * N_NODES];      // 128 MB weight matrix
__device__ float g_den[N_NODES];                       // row denominators

// mish(u) = u*(t^2+2t)/(t^2+2t+2), t=e^u
__device__ __forceinline__ float fast_mish(float u) {
    if (u > 30.f) return u;
    float t = __expf(u);
    float v = t * (t + 2.f);
    return u * __fdividef(v, v + 2.f);
}
__device__ __forceinline__ uint32_t smem_u32(const void* p) {
    uint32_t a;
    asm("{ .reg .u64 t; cvta.to.shared.u64 t, %1; cvt.u32.u64 %0, t; }" : "=r"(a) : "l"(p));
    return a;
}
#define SW128(x) ((x) ^ (((x) >> 3) & 0x70))

// ---- baseline-PTX tensor / async ops (compute_103-safe) --------------------
__device__ __forceinline__ void ldsm4(uint32_t* r, uint32_t addr) {
    asm volatile("ldmatrix.sync.aligned.m8n8.x4.shared.b16 {%0,%1,%2,%3}, [%4];"
                 : "=r"(r[0]), "=r"(r[1]), "=r"(r[2]), "=r"(r[3]) : "r"(addr));
}
__device__ __forceinline__ void mma_f16(float* d, const uint32_t* a,
                                        uint32_t b0, uint32_t b1) {
    asm volatile("mma.sync.aligned.m16n8k16.row.col.f32.f16.f16.f32 "
                 "{%0,%1,%2,%3}, {%4,%5,%6,%7}, {%8,%9}, {%0,%1,%2,%3};"
                 : "+f"(d[0]), "+f"(d[1]), "+f"(d[2]), "+f"(d[3])
                 : "r"(a[0]), "r"(a[1]), "r"(a[2]), "r"(a[3]), "r"(b0), "r"(b1));
}
__device__ __forceinline__ void cpa16(uint32_t s, const void* g) {
    asm volatile("cp.async.cg.shared.global [%0], [%1], 16;" :: "r"(s), "l"(g));
}
#define CPA_COMMIT() asm volatile("cp.async.commit_group;" ::: "memory")
#define CPA_WAIT0()  asm volatile("cp.async.wait_group 0;" ::: "memory")

// ---------------------------------------------------------------------------
// Kernel 1: h = x @ W  (FFMA SGEMM)
// ---------------------------------------------------------------------------
__global__ __launch_bounds__(256) void k_sgemm_xw(
    const float* __restrict__ X, const float* __restrict__ W)
{
    __shared__ float As[16][64];
    __shared__ float Bs[16][64];
    const int bn = blockIdx.x * 64, bm = blockIdx.y * 64;
    const int tid = threadIdx.x, tx = tid & 15, ty = tid >> 4;
    float acc[4][4];
#pragma unroll
    for (int r = 0; r < 4; r++)
#pragma unroll
        for (int c = 0; c < 4; c++) acc[r][c] = 0.f;
    for (int k0 = 0; k0 < FIN; k0 += 16) {
#pragma unroll
        for (int i = tid; i < 1024; i += 256) {
            int m = i >> 4, k = i & 15;
            As[k][m] = X[(size_t)(bm + m) * FIN + k0 + k];
        }
#pragma unroll
        for (int i = tid; i < 1024; i += 256) {
            int k = i >> 6, n = i & 63;
            Bs[k][n] = W[(size_t)(k0 + k) * FOUT + bn + n];
        }
        __syncthreads();
#pragma unroll
        for (int k = 0; k < 16; k++) {
            float4 a4 = *(const float4*)&As[k][ty * 4];
            float4 b4 = *(const float4*)&Bs[k][tx * 4];
            float a[4] = {a4.x, a4.y, a4.z, a4.w};
            float b[4] = {b4.x, b4.y, b4.z, b4.w};
#pragma unroll
            for (int r = 0; r < 4; r++)
#pragma unroll
                for (int c = 0; c < 4; c++) acc[r][c] = fmaf(a[r], b[c], acc[r][c]);
        }
        __syncthreads();
    }
#pragma unroll
    for (int r = 0; r < 4; r++) {
        float4 o = {acc[r][0], acc[r][1], acc[r][2], acc[r][3]};
        *(float4*)&g_h[(size_t)(bm + ty * 4 + r) * FOUT + bn + tx * 4] = o;
    }
}

// ---------------------------------------------------------------------------
// Kernel 2: s_src / s_dst
// ---------------------------------------------------------------------------
__global__ __launch_bounds__(256) void k_scores(const float* __restrict__ A)
{
    const int row = blockIdx.x * 8 + (threadIdx.x >> 5);
    const int lane = threadIdx.x & 31;
    const float4* h4 = (const float4*)(g_h + (size_t)row * FOUT);
    const float4* a14 = (const float4*)A;
    const float4* a24 = (const float4*)(A + FOUT);
    float s1 = 0.f, s2 = 0.f;
#pragma unroll
    for (int i = 0; i < 2; i++) {
        int idx = lane + i * 32;
        float4 h = h4[idx], a1 = a14[idx], a2 = a24[idx];
        s1 += h.x * a1.x + h.y * a1.y + h.z * a1.z + h.w * a1.w;
        s2 += h.x * a2.x + h.y * a2.y + h.z * a2.z + h.w * a2.w;
    }
#pragma unroll
    for (int off = 16; off; off >>= 1) {
        s1 += __shfl_down_sync(0xffffffffu, s1, off);
        s2 += __shfl_down_sync(0xffffffffu, s2, off);
    }
    if (lane == 0) { g_s[row] = s1; g_s[N_NODES + row] = s2; }
}

// ---------------------------------------------------------------------------
// Kernel 2b: global max of s_dst
// ---------------------------------------------------------------------------
__global__ __launch_bounds__(256) void k_smax()
{
    __shared__ float red[256];
    const int tid = threadIdx.x;
    float m = -1e30f;
    for (int i = tid; i < N_NODES; i += 256) m = fmaxf(m, g_s[N_NODES + i]);
    red[tid] = m;
    __syncthreads();
    for (int s = 128; s; s >>= 1) {
        if (tid < s) red[tid] = fmaxf(red[tid], red[tid + s]);
        __syncthreads();
    }
    if (tid == 0) g_smax = red[0];
}

// ---------------------------------------------------------------------------
// Kernel 3: h -> h^T fp16
// ---------------------------------------------------------------------------
__global__ __launch_bounds__(256) void k_hsplit()
{
    __shared__ float t[32][33];
    const int tid = threadIdx.x, tx = tid & 31, ty = tid >> 5;
    const int ibase = blockIdx.x * 32, nbase = blockIdx.y * 32;
#pragma unroll
    for (int r = 0; r < 4; r++)
        t[ty + r * 8][tx] = g_h[(size_t)(ibase + ty + r * 8) * FOUT + nbase + tx];
    __syncthreads();
#pragma unroll
    for (int r = 0; r < 4; r++) {
        int nl = ty + r * 8;
        g_hT[(size_t)(nbase + nl) * N_NODES + ibase + tx] = __float2half_rn(t[tx][nl]);
    }
}

// ---------------------------------------------------------------------------
// Kernel 3b: adj -> row-major bitmask  maskR[i][jw]
// ---------------------------------------------------------------------------
__global__ __launch_bounds__(256) void k_mask(const int* __restrict__ adj)
{
    __shared__ uint32_t sm[8][32];
    const int tid = threadIdx.x, lane = tid & 31, wid = tid >> 5;
    const int ibase = blockIdx.x * 32;
    const int jbase = blockIdx.y * 256;
#pragma unroll
    for (int rr = 0; rr < 4; rr++) {
        int il = wid * 4 + rr;
        const int* arow = adj + (size_t)(ibase + il) * N_NODES + jbase;
#pragma unroll
        for (int t = 0; t < 8; t++) {
            int av = arow[t * 32 + lane];
            uint32_t b = __ballot_sync(0xffffffffu, av > 0);
            if (lane == 0) sm[t][il] = b;
        }
    }
    __syncthreads();
    const int t = tid >> 5, il = tid & 31;
    g_maskR[(size_t)(ibase + il) * NWORDS + (jbase >> 5) + t] = sm[t][il];
}

// ---------------------------------------------------------------------------
// Kernel 4a: materialize W = exp(mish(s_i+s_j)-c_i) as fp16 + row denominators.
// Grid 256 CTAs x 256 thr. Warp owns rows blk*32 + wid*4 + rr.
// Denominator from fp16-ROUNDED values -> num/den consistent.
// ---------------------------------------------------------------------------
__global__ __launch_bounds__(256, 2) void k_wgen()
{
    const int lane = threadIdx.x & 31, wid = threadIdx.x >> 5;
    const float smax = g_smax;
    const float* __restrict__ sdst = g_s + N_NODES;
#pragma unroll
    for (int rr = 0; rr < 4; rr++) {
        const int row = blockIdx.x * 32 + wid * 4 + rr;
        const float ssrc = g_s[row];
        const float ci = fmaxf(ssrc + smax, 0.f);
        const uint32_t* __restrict__ mrow = g_maskR + (size_t)row * NWORDS;
        __half* __restrict__ wrow = g_w + (size_t)row * N_NODES;
        float rsum = 0.f;
#pragma unroll 4
        for (int q = 0; q < 64; q++) {
            const int j = q * 128 + lane * 4;
            const uint32_t mb = __ldg(mrow + (j >> 5)) >> ((lane & 7) * 4);
            float4 sv = __ldg((const float4*)(sdst + j));
            float w0 = (mb & 1u) ? __expf(fast_mish(ssrc + sv.x) - ci) : 0.f;
            float w1 = (mb & 2u) ? __expf(fast_mish(ssrc + sv.y) - ci) : 0.f;
            float w2 = (mb & 4u) ? __expf(fast_mish(ssrc + sv.z) - ci) : 0.f;
            float w3 = (mb & 8u) ? __expf(fast_mish(ssrc + sv.w) - ci) : 0.f;
            __half2 p01 = __floats2half2_rn(w0, w1);
            __half2 p23 = __floats2half2_rn(w2, w3);
            float2 f01 = __half22float2(p01);
            float2 f23 = __half22float2(p23);
            rsum += (f01.x + f01.y) + (f23.x + f23.y);
            uint2 pk = {*(uint32_t*)&p01, *(uint32_t*)&p23};
            *(uint2*)(wrow + j) = pk;
        }
#pragma unroll
        for (int o = 16; o; o >>= 1) rsum += __shfl_down_sync(0xffffffffu, rsum, o);
        if (lane == 0) g_den[row] = rsum;
    }
}

// ---------------------------------------------------------------------------
// Kernel 4b: pure fp16 GEMM  out = mish( (W @ hT^T) / den ).
// Grid (256, 2) = 512 CTAs, 256 thr, 4 CTAs/SM. CTA: M=32, N=128, K=8192.
// Stage (20KB x2): A [32x64] 4K | B [128x64] 16K.  Warp tile 16x32.
// ---------------------------------------------------------------------------
#define GST    20480
#define GOFF_B 4096
#define GEMM_SMEM (2 * GST)   // 40960 -> 4 CTAs/SM

__global__ __launch_bounds__(256, 4) void k_gemm(float* __restrict__ out)
{
    extern __shared__ char smem[];
    __shared__ float denf[32];
    const uint32_t sb = smem_u32(smem);
    const int tid = threadIdx.x;
    const int lane = tid & 31;
    const int wid = tid >> 5;

    const int row0  = blockIdx.x * 32;
    const int nbase = blockIdx.y * 128;

    // cp.async mappings
    const char* __restrict__ asrc =
        (const char*)(g_w + (size_t)(row0 + (tid >> 3)) * N_NODES) + (tid & 7) * 16;
    const uint32_t adst = SW128((uint32_t)(tid >> 3) * 128 + (tid & 7) * 16);
    const char* __restrict__ bsrc =
        (const char*)(g_hT + (size_t)(nbase + (tid & 127)) * N_NODES) + (tid >> 7) * 64;
    const uint32_t bbase = (uint32_t)(tid & 127) * 128 + (tid >> 7) * 64;

    // consumer mapping: warp (wm, wn): 16x32 tile of the 32x128 CTA tile
    const int wm = wid & 1;
    const int wn = wid >> 1;            // 0..3
    const int ksw = lane & 7;
    const int alsel = lane >> 4;
    const int bg = lane >> 3;
    const int kb0 = bg & 1;
    const uint32_t arow  = (uint32_t)(wm * 16 + (lane & 15)) * 128;
    const uint32_t brow0 = GOFF_B +
        (uint32_t)(wn * 32 + (lane & 7) + ((bg & 2) << 2)) * 128;

    if (tid < 32) denf[tid] = g_den[row0 + tid];

    float acc[4][4];
#pragma unroll
    for (int nt = 0; nt < 4; nt++)
#pragma unroll
        for (int q = 0; q < 4; q++) acc[nt][q] = 0.f;

    uint32_t Af[2][4];
    uint32_t Bf[2][2][4];

#define G_PROD(st_, c_)                                                          \
    {                                                                            \
        const uint32_t db = sb + (st_) * GST;                                    \
        cpa16(db + adst, asrc + (size_t)(c_) * 128);                             \
        const char* bs = bsrc + (size_t)(c_) * 128;                              \
        _Pragma("unroll")                                                        \
        for (int t = 0; t < 4; t++)                                              \
            cpa16(db + GOFF_B + SW128(bbase + t * 16), bs + t * 16);             \
        CPA_COMMIT();                                                            \
    }

#define G_FRAGS(base_, buf_, ks_)                                                \
    {                                                                            \
        const int kcA = (ks_) * 2 + alsel;                                       \
        ldsm4(Af[buf_], (base_) + arow + (uint32_t)((kcA ^ ksw) << 4));          \
        const int kcB = (ks_) * 2 + kb0;                                         \
        const uint32_t bo = (uint32_t)((kcB ^ ksw) << 4);                        \
        ldsm4(Bf[buf_][0], (base_) + brow0 + bo);                                \
        ldsm4(Bf[buf_][1], (base_) + brow0 + 2048 + bo);                         \
    }

    // ---- prologue ----
    G_PROD(0, 0);
    CPA_WAIT0();
    __syncthreads();

    for (int c = 0; c < NCHUNK; c++) {
        const int st = c & 1, ns = st ^ 1;
        const uint32_t sbase = sb + st * GST;
        if (c + 1 < NCHUNK) G_PROD(ns, c + 1);

        G_FRAGS(sbase, 0, 0);
#pragma unroll
        for (int ks = 0; ks < 4; ks++) {
            const int cur = ks & 1;
            if (ks < 3) G_FRAGS(sbase, cur ^ 1, ks + 1);
            mma_f16(acc[0], Af[cur], Bf[cur][0][0], Bf[cur][0][1]);
            mma_f16(acc[1], Af[cur], Bf[cur][0][2], Bf[cur][0][3]);
            mma_f16(acc[2], Af[cur], Bf[cur][1][0], Bf[cur][1][1]);
            mma_f16(acc[3], Af[cur], Bf[cur][1][2], Bf[cur][1][3]);
        }

        CPA_WAIT0();
        __syncthreads();
    }

    // ---- epilogue: normalize + mish -> out ----
    {
        const int lr = wm * 16 + (lane >> 2);
        const float inv0 = __fdividef(1.f, denf[lr]);
        const float inv1 = __fdividef(1.f, denf[lr + 8]);
        float* o0 = out + (size_t)(row0 + lr) * FOUT + nbase;
        float* o1 = out + (size_t)(row0 + lr + 8) * FOUT + nbase;
#pragma unroll
        for (int nt = 0; nt < 4; nt++) {
            const int col = wn * 32 + nt * 8 + (lane & 3) * 2;
            float2 v0 = {fast_mish(acc[nt][0] * inv0),
                         fast_mish(acc[nt][1] * inv0)};
            float2 v1 = {fast_mish(acc[nt][2] * inv1),
                         fast_mish(acc[nt][3] * inv1)};
            *(float2*)&o0[col] = v0;
            *(float2*)&o1[col] = v1;
        }
    }
#undef G_PROD
#undef G_FRAGS
}

// ---------------------------------------------------------------------------
extern "C" void kernel_launch(void* const* d_in, const int* in_sizes, int n_in,
                              void* d_out, int out_size)
{
    const float* x   = (const float*)d_in[0];   // [8192, 512]
    const int*   adj = (const int*)  d_in[1];   // [8192, 8192]
    const float* w   = (const float*)d_in[2];   // [512, 256]
    const float* a   = (const float*)d_in[3];   // [512, 1]
    float* out = (float*)d_out;                 // [8192, 256]

    cudaFuncSetAttribute(k_gemm, cudaFuncAttributeMaxDynamicSharedMemorySize,
                         GEMM_SMEM);

    k_mask<<<dim3(N_NODES / 32, N_NODES / 256), 256>>>(adj);
    k_sgemm_xw<<<dim3(FOUT / 64, N_NODES / 64), 256>>>(x, w);
    k_scores<<<N_NODES / 8, 256>>>(a);
    k_smax<<<1, 256>>>();
    k_hsplit<<<dim3(N_NODES / 32, FOUT / 32), 256>>>();
    k_wgen<<<256, 256>>>();
    k_gemm<<<dim3(256, 2), 256, GEMM_SMEM>>>(out);
}

// round 12
// speedup vs baseline: 1.6724x; 1.6724x over previous
#include <cuda_runtime.h>
#include <cuda_bf16.h>
#include <cuda_fp16.h>
#include <cstdint>

#define N_NODES 8192
#define FIN     512
#define FOUT    256
#define BKC     64                   // K-chunk
#define NCHUNK  (N_NODES / BKC)      // 128

// ---------------------------------------------------------------------------
// Device scratch
// ---------------------------------------------------------------------------
__device__ float g_h[(size_t)N_NODES * FOUT];          // 8 MB   h = x@W
__device__ float g_s[2 * N_NODES];                     // s_src | s_dst
__device__ float g_smax = -3.0e38f;                    // max_j s_dst (atomicMax)
__device__ __half g_hT[(size_t)FOUT * N_NODES];        // 4 MB   h^T fp16
__device__ __half g_w[(size_t)N_NODES * N_NODES];      // 128 MB weight matrix
__device__ float g_den[N_NODES];                       // row denominators

// mish(u) = u*(t^2+2t)/(t^2+2t+2), t=e^u
__device__ __forceinline__ float fast_mish(float u) {
    if (u > 30.f) return u;
    float t = __expf(u);
    float v = t * (t + 2.f);
    return u * __fdividef(v, v + 2.f);
}
__device__ __forceinline__ uint32_t smem_u32(const void* p) {
    uint32_t a;
    asm("{ .reg .u64 t; cvta.to.shared.u64 t, %1; cvt.u32.u64 %0, t; }" : "=r"(a) : "l"(p));
    return a;
}
__device__ __forceinline__ void atomic_max_float(float* addr, float val) {
    int old = __float_as_int(*addr);
    while (__int_as_float(old) < val) {
        int prev = atomicCAS((int*)addr, old, __float_as_int(val));
        if (prev == old) break;
        old = prev;
    }
}
#define SW128(x) ((x) ^ (((x) >> 3) & 0x70))

// ---- baseline-PTX tensor / async ops (compute_103-safe) --------------------
__device__ __forceinline__ void ldsm4(uint32_t* r, uint32_t addr) {
    asm volatile("ldmatrix.sync.aligned.m8n8.x4.shared.b16 {%0,%1,%2,%3}, [%4];"
                 : "=r"(r[0]), "=r"(r[1]), "=r"(r[2]), "=r"(r[3]) : "r"(addr));
}
__device__ __forceinline__ void mma_f16(float* d, const uint32_t* a,
                                        uint32_t b0, uint32_t b1) {
    asm volatile("mma.sync.aligned.m16n8k16.row.col.f32.f16.f16.f32 "
                 "{%0,%1,%2,%3}, {%4,%5,%6,%7}, {%8,%9}, {%0,%1,%2,%3};"
                 : "+f"(d[0]), "+f"(d[1]), "+f"(d[2]), "+f"(d[3])
                 : "r"(a[0]), "r"(a[1]), "r"(a[2]), "r"(a[3]), "r"(b0), "r"(b1));
}
__device__ __forceinline__ void cpa16(uint32_t s, const void* g) {
    asm volatile("cp.async.cg.shared.global [%0], [%1], 16;" :: "r"(s), "l"(g));
}
#define CPA_COMMIT() asm volatile("cp.async.commit_group;" ::: "memory")
#define CPA_WAIT1()  asm volatile("cp.async.wait_group 1;" ::: "memory")
#define CPA_WAIT0()  asm volatile("cp.async.wait_group 0;" ::: "memory")

// ---------------------------------------------------------------------------
// Launch 1: h = x @ W  (FFMA SGEMM) + fused h^T fp16 emission
// ---------------------------------------------------------------------------
__global__ __launch_bounds__(256) void k_sgemm_xw(
    const float* __restrict__ X, const float* __restrict__ W)
{
    __shared__ float As[16][64];
    __shared__ float Bs[16][64];
    __shared__ __half ht[64][66];
    const int bn = blockIdx.x * 64, bm = blockIdx.y * 64;
    const int tid = threadIdx.x, tx = tid & 15, ty = tid >> 4;
    float acc[4][4];
#pragma unroll
    for (int r = 0; r < 4; r++)
#pragma unroll
        for (int c = 0; c < 4; c++) acc[r][c] = 0.f;
    for (int k0 = 0; k0 < FIN; k0 += 16) {
#pragma unroll
        for (int i = tid; i < 1024; i += 256) {
            int m = i >> 4, k = i & 15;
            As[k][m] = X[(size_t)(bm + m) * FIN + k0 + k];
        }
#pragma unroll
        for (int i = tid; i < 1024; i += 256) {
            int k = i >> 6, n = i & 63;
            Bs[k][n] = W[(size_t)(k0 + k) * FOUT + bn + n];
        }
        __syncthreads();
#pragma unroll
        for (int k = 0; k < 16; k++) {
            float4 a4 = *(const float4*)&As[k][ty * 4];
            float4 b4 = *(const float4*)&Bs[k][tx * 4];
            float a[4] = {a4.x, a4.y, a4.z, a4.w};
            float b[4] = {b4.x, b4.y, b4.z, b4.w};
#pragma unroll
            for (int r = 0; r < 4; r++)
#pragma unroll
                for (int c = 0; c < 4; c++) acc[r][c] = fmaf(a[r], b[c], acc[r][c]);
        }
        __syncthreads();
    }
#pragma unroll
    for (int r = 0; r < 4; r++) {
        float4 o = {acc[r][0], acc[r][1], acc[r][2], acc[r][3]};
        *(float4*)&g_h[(size_t)(bm + ty * 4 + r) * FOUT + bn + tx * 4] = o;
#pragma unroll
        for (int c = 0; c < 4; c++)
            ht[ty * 4 + r][tx * 4 + c] = __float2half_rn(acc[r][c]);
    }
    __syncthreads();
    // coalesced transposed store: g_hT[n][m]
#pragma unroll
    for (int i = tid; i < 4096; i += 256) {
        const int n = i >> 6, m = i & 63;
        g_hT[(size_t)(bn + n) * N_NODES + bm + m] = ht[m][n];
    }
}

// ---------------------------------------------------------------------------
// Launch 2: s_src / s_dst + global max(s_dst)
// ---------------------------------------------------------------------------
__global__ __launch_bounds__(256) void k_scores(const float* __restrict__ A)
{
    const int row = blockIdx.x * 8 + (threadIdx.x >> 5);
    const int lane = threadIdx.x & 31;
    const float4* h4 = (const float4*)(g_h + (size_t)row * FOUT);
    const float4* a14 = (const float4*)A;
    const float4* a24 = (const float4*)(A + FOUT);
    float s1 = 0.f, s2 = 0.f;
#pragma unroll
    for (int i = 0; i < 2; i++) {
        int idx = lane + i * 32;
        float4 h = h4[idx], a1 = a14[idx], a2 = a24[idx];
        s1 += h.x * a1.x + h.y * a1.y + h.z * a1.z + h.w * a1.w;
        s2 += h.x * a2.x + h.y * a2.y + h.z * a2.z + h.w * a2.w;
    }
#pragma unroll
    for (int off = 16; off; off >>= 1) {
        s1 += __shfl_down_sync(0xffffffffu, s1, off);
        s2 += __shfl_down_sync(0xffffffffu, s2, off);
    }
    if (lane == 0) {
        g_s[row] = s1;
        g_s[N_NODES + row] = s2;
        atomic_max_float(&g_smax, s2);
    }
}

// ---------------------------------------------------------------------------
// Launch 3: W = exp(mish(s_i+s_j)-c_i) fp16 + row denominators (adj read raw).
// One warp per row; lane reads int4 of adj (coalesced 512B per warp).
// Denominator from fp16-ROUNDED values -> num/den consistent.
// ---------------------------------------------------------------------------
__global__ __launch_bounds__(256) void k_wgen(const int* __restrict__ adj)
{
    const int lane = threadIdx.x & 31, wid = threadIdx.x >> 5;
    const int row = blockIdx.x * 8 + wid;
    const float ssrc = g_s[row];
    const float ci = fmaxf(ssrc + g_smax, 0.f);
    const float* __restrict__ sdst = g_s + N_NODES;
    const int4* __restrict__ arow = (const int4*)(adj + (size_t)row * N_NODES);
    __half* __restrict__ wrow = g_w + (size_t)row * N_NODES;
    float rsum = 0.f;
#pragma unroll 4
    for (int q = 0; q < 64; q++) {
        const int j4 = q * 32 + lane;        // int4 / float4 index
        int4   av = __ldg(arow + j4);
        float4 sv = __ldg((const float4*)sdst + j4);
        float w0 = (av.x > 0) ? __expf(fast_mish(ssrc + sv.x) - ci) : 0.f;
        float w1 = (av.y > 0) ? __expf(fast_mish(ssrc + sv.y) - ci) : 0.f;
        float w2 = (av.z > 0) ? __expf(fast_mish(ssrc + sv.z) - ci) : 0.f;
        float w3 = (av.w > 0) ? __expf(fast_mish(ssrc + sv.w) - ci) : 0.f;
        __half2 p01 = __floats2half2_rn(w0, w1);
        __half2 p23 = __floats2half2_rn(w2, w3);
        float2 f01 = __half22float2(p01);
        float2 f23 = __half22float2(p23);
        rsum += (f01.x + f01.y) + (f23.x + f23.y);
        uint2 pk = {*(uint32_t*)&p01, *(uint32_t*)&p23};
        *(uint2*)(wrow + j4 * 4) = pk;
    }
#pragma unroll
    for (int o = 16; o; o >>= 1) rsum += __shfl_down_sync(0xffffffffu, rsum, o);
    if (lane == 0) g_den[row] = rsum;
}

// ---------------------------------------------------------------------------
// Launch 4: fp16 GEMM  out = mish( (W @ hT^T) / den ).
// Grid (128, 2) = 256 CTAs, 256 thr. CTA: M=64, N=128, K=8192.
// Stage (24KB x3): A [64x64] 8K | B [128x64] 16K. 3-stage cp.async, wait_group 1.
// Warp grid 2(m) x 4(n); warp tile 32x32.
// ---------------------------------------------------------------------------
#define GST    24576
#define GOFF_B 8192
#define GEMM_SMEM (3 * GST)   // 73728 -> 2 CTAs/SM

__global__ __launch_bounds__(256, 2) void k_gemm(float* __restrict__ out)
{
    extern __shared__ char smem[];
    __shared__ float denf[64];
    const uint32_t sb = smem_u32(smem);
    const int tid = threadIdx.x;
    const int lane = tid & 31;
    const int wid = tid >> 5;

    const int row0  = blockIdx.x * 64;
    const int nbase = blockIdx.y * 128;

    // cp.async mappings: A = 64 rows x 128B (2 segs/thread), B = 128 rows x 128B (4/thread)
    const int ar = tid >> 3;
    const uint32_t aoff = (uint32_t)(tid & 7) * 16;
    const char* __restrict__ asrc0 = (const char*)(g_w + (size_t)(row0 + ar) * N_NODES) + aoff;
    const char* __restrict__ asrc1 = (const char*)(g_w + (size_t)(row0 + ar + 32) * N_NODES) + aoff;
    const uint32_t adst0 = SW128((uint32_t)ar * 128 + aoff);
    const uint32_t adst1 = SW128((uint32_t)(ar + 32) * 128 + aoff);
    const int brow_p = tid & 127, bhalf = tid >> 7;
    const char* __restrict__ bsrc =
        (const char*)(g_hT + (size_t)(nbase + brow_p) * N_NODES) + bhalf * 64;
    const uint32_t bb = (uint32_t)brow_p * 128 + bhalf * 64;

    // consumer mapping: warp (wm, wn): 32x32 tile
    const int wm = wid & 1;
    const int wn = wid >> 1;            // 0..3
    const int ksw = lane & 7;
    const int alsel = lane >> 4;
    const int bg = lane >> 3;
    const int kb0 = bg & 1;
    const uint32_t arow  = (uint32_t)(wm * 32 + (lane & 15)) * 128;
    const uint32_t brow0 = GOFF_B +
        (uint32_t)(wn * 32 + (lane & 7) + ((bg & 2) << 2)) * 128;

    if (tid < 64) denf[tid] = g_den[row0 + tid];

    float acc[2][4][4];
#pragma unroll
    for (int mt = 0; mt < 2; mt++)
#pragma unroll
        for (int nt = 0; nt < 4; nt++)
#pragma unroll
            for (int q = 0; q < 4; q++) acc[mt][nt][q] = 0.f;

    uint32_t Af[2][2][4];
    uint32_t Bf[2][2][4];

#define G_PROD(st_, c_)                                                          \
    {                                                                            \
        const uint32_t db = sb + (st_) * GST;                                    \
        cpa16(db + adst0, asrc0 + (size_t)(c_) * 128);                           \
        cpa16(db + adst1, asrc1 + (size_t)(c_) * 128);                           \
        const char* bs = bsrc + (size_t)(c_) * 128;                              \
        _Pragma("unroll")                                                        \
        for (int t = 0; t < 4; t++)                                              \
            cpa16(db + GOFF_B + SW128(bb + t * 16), bs + t * 16);                \
        CPA_COMMIT();                                                            \
    }

// A fragments: consecutive m16 fragments are 16 rows apart = 2048 bytes.
#define G_FRAGS(base_, buf_, ks_)                                                \
    {                                                                            \
        const int kcA = (ks_) * 2 + alsel;                                       \
        const uint32_t ao = (uint32_t)((kcA ^ ksw) << 4);                        \
        ldsm4(Af[buf_][0], (base_) + arow + ao);                                 \
        ldsm4(Af[buf_][1], (base_) + arow + 2048 + ao);                          \
        const int kcB = (ks_) * 2 + kb0;                                         \
        const uint32_t bo = (uint32_t)((kcB ^ ksw) << 4);                        \
        ldsm4(Bf[buf_][0], (base_) + brow0 + bo);                                \
        ldsm4(Bf[buf_][1], (base_) + brow0 + 2048 + bo);                         \
    }

    // ---- prologue: 2 chunks in flight ----
    G_PROD(0, 0);
    G_PROD(1, 1);

    for (int c = 0; c < NCHUNK; c++) {
        const int st = c % 3;
        if (c + 1 >= NCHUNK) { CPA_WAIT0(); } else { CPA_WAIT1(); }
        __syncthreads();
        if (c + 2 < NCHUNK) G_PROD((c + 2) % 3, c + 2);

        const uint32_t sbase = sb + st * GST;
        G_FRAGS(sbase, 0, 0);
#pragma unroll
        for (int ks = 0; ks < 4; ks++) {
            const int cur = ks & 1;
            if (ks < 3) G_FRAGS(sbase, cur ^ 1, ks + 1);
            mma_f16(acc[0][0], Af[cur][0], Bf[cur][0][0], Bf[cur][0][1]);
            mma_f16(acc[0][1], Af[cur][0], Bf[cur][0][2], Bf[cur][0][3]);
            mma_f16(acc[0][2], Af[cur][0], Bf[cur][1][0], Bf[cur][1][1]);
            mma_f16(acc[0][3], Af[cur][0], Bf[cur][1][2], Bf[cur][1][3]);
            mma_f16(acc[1][0], Af[cur][1], Bf[cur][0][0], Bf[cur][0][1]);
            mma_f16(acc[1][1], Af[cur][1], Bf[cur][0][2], Bf[cur][0][3]);
            mma_f16(acc[1][2], Af[cur][1], Bf[cur][1][0], Bf[cur][1][1]);
            mma_f16(acc[1][3], Af[cur][1], Bf[cur][1][2], Bf[cur][1][3]);
        }
    }

    // ---- epilogue: normalize + mish -> out ----
#pragma unroll
    for (int mt = 0; mt < 2; mt++) {
        const int lr = wm * 32 + mt * 16 + (lane >> 2);
        const float inv0 = __fdividef(1.f, denf[lr]);
        const float inv1 = __fdividef(1.f, denf[lr + 8]);
        float* o0 = out + (size_t)(row0 + lr) * FOUT + nbase;
        float* o1 = out + (size_t)(row0 + lr + 8) * FOUT + nbase;
#pragma unroll
        for (int nt = 0; nt < 4; nt++) {
            const int col = wn * 32 + nt * 8 + (lane & 3) * 2;
            float2 v0 = {fast_mish(acc[mt][nt][0] * inv0),
                         fast_mish(acc[mt][nt][1] * inv0)};
            float2 v1 = {fast_mish(acc[mt][nt][2] * inv1),
                         fast_mish(acc[mt][nt][3] * inv1)};
            *(float2*)&o0[col] = v0;
            *(float2*)&o1[col] = v1;
        }
    }
#undef G_PROD
#undef G_FRAGS
}

// ---------------------------------------------------------------------------
extern "C" void kernel_launch(void* const* d_in, const int* in_sizes, int n_in,
                              void* d_out, int out_size)
{
    const float* x   = (const float*)d_in[0];   // [8192, 512]
    const int*   adj = (const int*)  d_in[1];   // [8192, 8192]
    const float* w   = (const float*)d_in[2];   // [512, 256]
    const float* a   = (const float*)d_in[3];   // [512, 1]
    float* out = (float*)d_out;                 // [8192, 256]

    cudaFuncSetAttribute(k_gemm, cudaFuncAttributeMaxDynamicSharedMemorySize,
                         GEMM_SMEM);

    k_sgemm_xw<<<dim3(FOUT / 64, N_NODES / 64), 256>>>(x, w);   // launch 1
    k_scores<<<N_NODES / 8, 256>>>(a);                          // launch 2
    k_wgen<<<N_NODES / 8, 256>>>(adj);                          // launch 3
    k_gemm<<<dim3(128, 2), 256, GEMM_SMEM>>>(out);              // launch 4 (profiled)
}